// round 5
// baseline (speedup 1.0000x reference)
#include <cuda_runtime.h>
#include <math.h>

#define NVEC 131072
#define DIMS 64
#define KCODES 256
#define NBLK 148
#define NTHR 256

// Output packing (tuple flattened, fp32):
// loss(1), out(32*64*64*64), perplexity(1), idx(131072), new_emb_w(16384), new_cs(256), new_ema_w(16384)
#define OFF_LOSS 0
#define OFF_OUT  1
#define OFF_PERP 8388609
#define OFF_IDX  8388610
#define OFF_EMBW 8519682
#define OFF_CS   8536066
#define OFF_EMAW 8536322

// scratch: [0,16384) dw, [16384,16640) counts, [16640] loss accumulator
__device__ float g_scr[16641];

typedef unsigned long long ull;

__device__ __forceinline__ ull ffma2(ull a, ull b, ull c) {
    ull d;
    asm("fma.rn.f32x2 %0, %1, %2, %3;" : "=l"(d) : "l"(a), "l"(b), "l"(c));
    return d;
}
__device__ __forceinline__ ull packdup(float v) {
    ull r;
    asm("mov.b64 %0, {%1, %1};" : "=l"(r) : "f"(v));
    return r;
}
__device__ __forceinline__ float lo32(ull v) { return __uint_as_float((unsigned)v); }
__device__ __forceinline__ float hi32(ull v) { return __uint_as_float((unsigned)(v >> 32)); }

// ---------------------------------------------------------------------------
// Kernel 0: zero scratch (graph replays must be deterministic)
// ---------------------------------------------------------------------------
__global__ void vq_zero() {
    int i = blockIdx.x * blockDim.x + threadIdx.x;
    if (i < 16641) g_scr[i] = 0.f;
}

// ---------------------------------------------------------------------------
// Kernel 1: distances + argmin + quantized output + loss + dw/count partials
// ---------------------------------------------------------------------------
__global__ void __launch_bounds__(NTHR, 1)
vq_main(const float* __restrict__ in, const float* __restrict__ emb,
        float* __restrict__ dout) {
    extern __shared__ float sm[];
    float* s_e2  = sm;             // 16384: pair-interleaved codebook {e[2p][c], e[2p+1][c]}
    float* s_eg  = sm + 16384;     // 16384: rotation-swizzled copy for gather
    float* s_dw  = sm + 32768;     // 16384: per-block dw accumulator
    float* s_h   = sm + 49152;     // 256:   0.5*||e_k||^2
    float* s_cnt = sm + 49408;     // 256:   per-block counts
    float* s_red = sm + 49664;     // 32:    loss reduction
    const ull* s_e2u = (const ull*)s_e2;

    const int tid = threadIdx.x;
    const int lane = tid & 31;

    // Load codebook into both shared layouts; zero accumulators.
    for (int i = tid; i < 16384; i += NTHR) {
        float v = emb[i];
        int k = i >> 6, c = i & 63;
        s_e2[((k >> 1) << 7) + (c << 1) + (k & 1)] = v;
        s_eg[(k << 6) + ((c + k) & 63)] = v;
        s_dw[i] = 0.f;
    }
    if (tid < KCODES) {
        float s = 0.f;
        const float* er = emb + (tid << 6);
#pragma unroll
        for (int c = 0; c < 64; c++) s += er[c] * er[c];
        s_h[tid] = 0.5f * s;
        s_cnt[tid] = 0.f;
    }
    __syncthreads();

    float lossacc = 0.f;

    // NVEC, NBLK*NTHR and warp bases are all multiples of 32 => every warp is
    // convergent at full mask throughout the n-loop (uniform trip count).
    for (int n = blockIdx.x * NTHR + tid; n < NVEC; n += NBLK * NTHR) {
        int b = n >> 12, hw = n & 4095;
        const float* xp = in + b * 262144 + hw;

        // Load x (strided by 4096 over channels), packed as {x,x} f32x2.
        ull x2[64];
#pragma unroll
        for (int c = 0; c < 64; c++) x2[c] = packdup(xp[c << 12]);

        // argmin_k (0.5*||e_k||^2 - x.e_k)  ==  argmin_k ||x - e_k||^2
        float best = 3.402823466e+38f;
        float best2 = 3.402823466e+38f;
        int bestk = 0;
#pragma unroll 1
        for (int kb = 0; kb < KCODES; kb += 8) {
            int p0 = kb >> 1;  // pair index; 4 pairs = 8 codes per group
            const ull* e0 = s_e2u + (p0 << 6);
            const ull* e1 = e0 + 64;
            const ull* e2 = e0 + 128;
            const ull* e3 = e0 + 192;
            ull a0 = 0, a1 = 0, a2 = 0, a3 = 0;
#pragma unroll
            for (int c = 0; c < 64; c += 2) {
                ulonglong2 q0 = *(const ulonglong2*)(e0 + c);
                ulonglong2 q1 = *(const ulonglong2*)(e1 + c);
                ulonglong2 q2 = *(const ulonglong2*)(e2 + c);
                ulonglong2 q3 = *(const ulonglong2*)(e3 + c);
                a0 = ffma2(x2[c], q0.x, a0);
                a1 = ffma2(x2[c], q1.x, a1);
                a2 = ffma2(x2[c], q2.x, a2);
                a3 = ffma2(x2[c], q3.x, a3);
                a0 = ffma2(x2[c + 1], q0.y, a0);
                a1 = ffma2(x2[c + 1], q1.y, a1);
                a2 = ffma2(x2[c + 1], q2.y, a2);
                a3 = ffma2(x2[c + 1], q3.y, a3);
            }
            float sc;
#define VQ_CAND(KOFF, VAL)                                         \
            sc = s_h[kb + KOFF] - (VAL);                           \
            if (sc < best) { best2 = best; best = sc; bestk = kb + KOFF; } \
            else if (sc < best2) { best2 = sc; }
            VQ_CAND(0, lo32(a0)) VQ_CAND(1, hi32(a0))
            VQ_CAND(2, lo32(a1)) VQ_CAND(3, hi32(a1))
            VQ_CAND(4, lo32(a2)) VQ_CAND(5, hi32(a2))
            VQ_CAND(6, lo32(a3)) VQ_CAND(7, hi32(a3))
#undef VQ_CAND
        }

        // Near-tie fixup: fp32 score noise is ~2e-5; if the best/second gap is
        // within 4e-3 (200x margin), recompute this vector's distances exactly
        // in fp64, warp-cooperatively (each lane owns 8 codes, k = kk*32+lane
        // => conflict-free swizzled LDS). Tie band 3e-6 -> lower index, to
        // mirror argmin's first-min rule on reference-side rounding ties.
        unsigned fmask = __ballot_sync(0xffffffffu, (best2 - best) < 4e-3f);
        while (fmask) {
            int src = __ffs(fmask) - 1; fmask &= fmask - 1;
            int ns = n - lane + src;
            const float* xs = in + (ns >> 12) * 262144 + (ns & 4095);
            double bd = 1e300; int bk = 0;
#pragma unroll 1
            for (int kk = 0; kk < 8; kk++) {
                int k = kk * 32 + lane;
                const float* er = s_eg + (k << 6);
                double sA = 0.0, sB = 0.0;
#pragma unroll
                for (int c = 0; c < 64; c += 2) {
                    double d0 = (double)xs[c << 12] - (double)er[(c + k) & 63];
                    double d1 = (double)xs[(c + 1) << 12] - (double)er[(c + 1 + k) & 63];
                    sA += d0 * d0; sB += d1 * d1;
                }
                double s = sA + sB;
                if (s < bd - 3e-6 || (s < bd + 3e-6 && k < bk)) { bd = s; bk = k; }
            }
#pragma unroll
            for (int o = 16; o; o >>= 1) {
                double od = __shfl_xor_sync(0xffffffffu, bd, o);
                int ok = __shfl_xor_sync(0xffffffffu, bk, o);
                if (od < bd - 3e-6 || (od < bd + 3e-6 && ok < bk)) { bd = od; bk = ok; }
            }
            if (lane == src) bestk = bk;
        }

        // Quantized output (NCHW) + loss contribution. The reference's
        // straight-through output is fl(x + fl(q - x)), not q — reproduce it
        // bit-for-bit. Gather from swizzled copy (rotation spreads banks).
        float* op = dout + OFF_OUT + b * 262144 + hw;
        int kb64 = bestk << 6;
#pragma unroll
        for (int c = 0; c < 64; c++) {
            float e = s_eg[kb64 + ((c + bestk) & 63)];
            float xv = lo32(x2[c]);
            float df = e - xv;
            lossacc += df * df;
            op[c << 12] = xv + df;
        }
        dout[OFF_IDX + n] = (float)bestk;

        // dw accumulation: lane-staggered column order => bank-conflict-free.
#pragma unroll
        for (int c0 = 0; c0 < 64; c0++) {
            int c = (c0 + lane) & 63;
            atomicAdd(s_dw + kb64 + c, lo32(x2[c]));
        }
        atomicAdd(s_cnt + bestk, 1.0f);
    }
    __syncthreads();

    // Flush per-block partials to global scratch.
    for (int i = tid; i < 16384; i += NTHR) atomicAdd(&g_scr[i], s_dw[i]);
    if (tid < KCODES) atomicAdd(&g_scr[16384 + tid], s_cnt[tid]);

    // Loss: warp reduce -> shared -> one atomic per block.
#pragma unroll
    for (int o = 16; o; o >>= 1) lossacc += __shfl_xor_sync(0xffffffffu, lossacc, o);
    if (lane == 0) s_red[tid >> 5] = lossacc;
    __syncthreads();
    if (tid == 0) {
        float s = 0.f;
        for (int w = 0; w < NTHR / 32; w++) s += s_red[w];
        atomicAdd(&g_scr[16640], s);
    }
}

// ---------------------------------------------------------------------------
// Kernel 2: finalize EMA updates, perplexity, loss
// ---------------------------------------------------------------------------
__global__ void vq_finalize(const float* __restrict__ cs_in,
                            const float* __restrict__ emaw_in,
                            float* __restrict__ dout) {
    __shared__ float s_cs[256];
    __shared__ float s_red[8];
    int t = threadIdx.x;
    int lane = t & 31, w = t >> 5;

    float cnt = g_scr[16384 + t];
    float ncs = cs_in[t] * 0.99f + 0.01f * cnt;

    // n = sum(new_cs)
    float v = ncs;
#pragma unroll
    for (int o = 16; o; o >>= 1) v += __shfl_xor_sync(0xffffffffu, v, o);
    if (lane == 0) s_red[w] = v;
    __syncthreads();
    float nsum = 0.f;
#pragma unroll
    for (int j = 0; j < 8; j++) nsum += s_red[j];

    float csf = (ncs + 1e-5f) / (nsum + 256.f * 1e-5f) * nsum;
    s_cs[t] = csf;
    dout[OFF_CS + t] = csf;

    // perplexity
    float avg = cnt * (1.0f / (float)NVEC);
    float term = avg * logf(avg + 1e-10f);
    float e = term;
#pragma unroll
    for (int o = 16; o; o >>= 1) e += __shfl_xor_sync(0xffffffffu, e, o);
    __syncthreads();  // protect s_red reuse
    if (lane == 0) s_red[w] = e;
    __syncthreads();
    if (t == 0) {
        float es = 0.f;
        for (int j = 0; j < 8; j++) es += s_red[j];
        dout[OFF_PERP] = expf(-es);
        dout[OFF_LOSS] = 0.25f * g_scr[16640] * (1.0f / 8388608.0f);
    }

    // new_ema_w and new_emb_w (s_cs already visible via syncs above)
    for (int i = t; i < 16384; i += 256) {
        float ew = emaw_in[i] * 0.99f + 0.01f * g_scr[i];
        dout[OFF_EMAW + i] = ew;
        dout[OFF_EMBW + i] = ew / s_cs[i >> 6];
    }
}

// ---------------------------------------------------------------------------
extern "C" void kernel_launch(void* const* d_in, const int* in_sizes, int n_in,
                              void* d_out, int out_size) {
    const float* in   = (const float*)d_in[0];
    const float* emb  = (const float*)d_in[1];
    const float* cs   = (const float*)d_in[2];
    const float* emaw = (const float*)d_in[3];
    float* dout = (float*)d_out;

    const int smem = 49696 * 4;  // 198784 B dynamic shared
    cudaFuncSetAttribute(vq_main, cudaFuncAttributeMaxDynamicSharedMemorySize, smem);

    vq_zero<<<(16641 + 255) / 256, 256>>>();
    vq_main<<<NBLK, NTHR, smem>>>(in, emb, dout);
    vq_finalize<<<1, 256>>>(cs, emaw, dout);
}